// round 4
// baseline (speedup 1.0000x reference)
#include <cuda_runtime.h>
#include <cuda_fp16.h>
#include <cstdint>

#define TDIM 8192
#define DDIM 4096

// ---- device scratch (allocation-free rule: __device__ globals) ----
static __device__ __half g_w1[(size_t)DDIM * DDIM];
static __device__ __half g_w2[(size_t)DDIM * DDIM];
static __device__ __half g_a[(size_t)TDIM * DDIM];
static __device__ __half g_h[(size_t)TDIM * DDIM];

__constant__ float c_lut[16] = {0.f, 0.5f, 1.f, 1.5f, 2.f, 3.f, 4.f, 6.f,
                                -0.f, -0.5f, -1.f, -1.5f, -2.f, -3.f, -4.f, -6.f};

// ---- dequant: int32 codes [D,D] * 2^scales [D,D/32] -> fp16 [D,D] (exact) ----
__global__ void dequant_kernel(const int* __restrict__ codes,
                               const float* __restrict__ scales,
                               int which) {
    __half* __restrict__ out = which ? g_w2 : g_w1;
    size_t base = ((size_t)blockIdx.x * blockDim.x + threadIdx.x) * 4;
    int4 c = *reinterpret_cast<const int4*>(codes + base);
    size_t o = base >> 12;
    int i = (int)(base & 4095);
    float s = __ldg(scales + o * (DDIM / 32) + (i >> 5));
    __half2 p0 = __floats2half2_rn(c_lut[c.x & 15] * s, c_lut[c.y & 15] * s);
    __half2 p1 = __floats2half2_rn(c_lut[c.z & 15] * s, c_lut[c.w & 15] * s);
    *reinterpret_cast<__half2*>(out + base) = p0;
    *reinterpret_cast<__half2*>(out + base + 2) = p1;
}

// ---- convert fp32 x -> fp16 ----
__global__ void split_kernel(const float* __restrict__ x) {
    size_t base = ((size_t)blockIdx.x * blockDim.x + threadIdx.x) * 4;
    float4 v = *reinterpret_cast<const float4*>(x + base);
    *reinterpret_cast<__half2*>(g_a + base) = __floats2half2_rn(v.x, v.y);
    *reinterpret_cast<__half2*>(g_a + base + 2) = __floats2half2_rn(v.z, v.w);
}

__device__ __forceinline__ void ldmat4(uint32_t addr, uint32_t& d0, uint32_t& d1,
                                       uint32_t& d2, uint32_t& d3) {
    asm volatile("ldmatrix.sync.aligned.m8n8.x4.shared.b16 {%0,%1,%2,%3}, [%4];\n"
                 : "=r"(d0), "=r"(d1), "=r"(d2), "=r"(d3) : "r"(addr));
}

__device__ __forceinline__ void mma16816(float* c, const uint32_t* a, const uint32_t* b) {
    asm volatile(
        "mma.sync.aligned.m16n8k16.row.col.f32.f16.f16.f32 "
        "{%0,%1,%2,%3}, {%4,%5,%6,%7}, {%8,%9}, {%0,%1,%2,%3};\n"
        : "+f"(c[0]), "+f"(c[1]), "+f"(c[2]), "+f"(c[3])
        : "r"(a[0]), "r"(a[1]), "r"(a[2]), "r"(a[3]), "r"(b[0]), "r"(b[1]));
}

__device__ __forceinline__ void cp16(uint32_t saddr, const void* gaddr) {
    asm volatile("cp.async.cg.shared.global [%0], [%1], 16;\n"
                 :: "r"(saddr), "l"(gaddr));
}

// ================= pipelined GEMM =================
// CTA tile 128(M) x 256(N), BK=64, 3-stage cp.async pipeline.
// 8 warps = 2(M) x 4(N), 64x64 per warp.
#define BK 64
#define STAGES 3
#define NCH (DDIM / BK)
#define W_BYTES (256 * BK * 2)
#define A_BYTES (128 * BK * 2)
#define STAGE_BYTES (W_BYTES + A_BYTES)
#define SMEM_BYTES (STAGES * STAGE_BYTES)

// smem layout per tile: 128B rows (64 halves), 8 chunks of 16B,
// chunk ^= (row & 7)  -> conflict-free for ldmatrix 8-lane wavefronts.
template <int LAYER>
__global__ void __launch_bounds__(256, 1)
gemm_kernel(const float* __restrict__ bias, float* __restrict__ outf) {
    extern __shared__ char dsm[];
    const __half* __restrict__ A = (LAYER == 0) ? g_a : g_h;
    const __half* __restrict__ W = (LAYER == 0) ? g_w1 : g_w2;

    __shared__ float sBias[256];

    const int tid = threadIdx.x;
    const int lane = tid & 31;
    const int wid = tid >> 5;
    const int wm = wid & 1;
    const int wn = wid >> 1;
    const int o0 = blockIdx.x * 256;
    const int t0 = blockIdx.y * 128;

    sBias[tid] = __ldg(bias + o0 + tid);

    const uint32_t sdyn = (uint32_t)__cvta_generic_to_shared(dsm);

    // ---- loader maps ----
    // W: thread tid -> row tid (0..255), 8 chunks of 16B
    const int wRow = tid;
    const __half* gW = W + (size_t)(o0 + wRow) * DDIM;
    uint32_t wSoff[8];
#pragma unroll
    for (int c = 0; c < 8; c++)
        wSoff[c] = (uint32_t)(wRow * 128 + ((c ^ (wRow & 7)) << 4));
    // A: thread -> row tid>>1 (0..127), 4 chunks starting at (tid&1)*4
    const int aRow_l = tid >> 1;
    const int aCb = (tid & 1) * 4;
    const __half* gA = A + (size_t)(t0 + aRow_l) * DDIM + aCb * 8;
    uint32_t aSoff[4];
#pragma unroll
    for (int c = 0; c < 4; c++)
        aSoff[c] = (uint32_t)(aRow_l * 128 + (((aCb + c) ^ (aRow_l & 7)) << 4));

    // ---- mma fragment address components ----
    const int aRow = lane & 15;
    const int aKC = lane >> 4;
    const int bRow = (lane & 7) + ((lane >> 4) << 3);
    const int bKC = (lane >> 3) & 1;
    uint32_t aOff[4];
    int aXor[4];
#pragma unroll
    for (int mf = 0; mf < 4; mf++) {
        int row = wm * 64 + mf * 16 + aRow;
        aOff[mf] = (uint32_t)(row * 128);
        aXor[mf] = row & 7;
    }
    uint32_t bOff[4];
    int bXor[4];
#pragma unroll
    for (int nb = 0; nb < 4; nb++) {
        int row = wn * 64 + nb * 16 + bRow;
        bOff[nb] = (uint32_t)(row * 128);
        bXor[nb] = row & 7;
    }

    float acc[4][8][4];
#pragma unroll
    for (int i = 0; i < 4; i++)
#pragma unroll
        for (int j = 0; j < 8; j++)
#pragma unroll
            for (int k = 0; k < 4; k++) acc[i][j][k] = 0.f;

    // ---- stage loader ----
    auto load_stage = [&](int s, int k0) {
        const uint32_t wb = sdyn + s * STAGE_BYTES;
        const uint32_t ab = wb + W_BYTES;
#pragma unroll
        for (int c = 0; c < 8; c++) cp16(wb + wSoff[c], gW + k0 + c * 8);
#pragma unroll
        for (int c = 0; c < 4; c++) cp16(ab + aSoff[c], gA + k0 + c * 8);
        asm volatile("cp.async.commit_group;\n" ::: "memory");
    };

    // prologue: prefetch chunks 0..STAGES-2
#pragma unroll
    for (int s = 0; s < STAGES - 1; s++) load_stage(s, s * BK);

    for (int i = 0; i < NCH; i++) {
        if (i < NCH - 1)
            asm volatile("cp.async.wait_group 1;\n" ::: "memory");
        else
            asm volatile("cp.async.wait_group 0;\n" ::: "memory");
        __syncthreads();
        if (i + STAGES - 1 < NCH)
            load_stage((i + STAGES - 1) % STAGES, (i + STAGES - 1) * BK);

        const uint32_t wb = sdyn + (i % STAGES) * STAGE_BYTES;
        const uint32_t ab = wb + W_BYTES;
#pragma unroll
        for (int kk = 0; kk < 4; kk++) {
            const int kc = kk * 2;
            uint32_t b[8][2];
#pragma unroll
            for (int nb = 0; nb < 4; nb++) {
                uint32_t addr = wb + bOff[nb] + (uint32_t)(((kc + bKC) ^ bXor[nb]) << 4);
                ldmat4(addr, b[nb * 2][0], b[nb * 2][1], b[nb * 2 + 1][0],
                       b[nb * 2 + 1][1]);
            }
            uint32_t a[4][4];
#pragma unroll
            for (int mf = 0; mf < 4; mf++) {
                uint32_t addr = ab + aOff[mf] + (uint32_t)(((kc + aKC) ^ aXor[mf]) << 4);
                ldmat4(addr, a[mf][0], a[mf][1], a[mf][2], a[mf][3]);
            }
#pragma unroll
            for (int mf = 0; mf < 4; mf++)
#pragma unroll
                for (int nf = 0; nf < 8; nf++) mma16816(acc[mf][nf], a[mf], b[nf]);
        }
    }

    // ---- epilogue ----
    const int gr = lane >> 2;
    const int tc2 = (lane & 3) * 2;
#pragma unroll
    for (int mf = 0; mf < 4; mf++) {
        const int row = t0 + wm * 64 + mf * 16 + gr;
#pragma unroll
        for (int nf = 0; nf < 8; nf++) {
            const int colL = wn * 64 + nf * 8 + tc2;
            const int col = o0 + colL;
            float bv0 = sBias[colL];
            float bv1 = sBias[colL + 1];
            float v00 = acc[mf][nf][0] + bv0;
            float v01 = acc[mf][nf][1] + bv1;
            float v10 = acc[mf][nf][2] + bv0;
            float v11 = acc[mf][nf][3] + bv1;
            if (LAYER == 0) {
                *reinterpret_cast<__half2*>(g_h + (size_t)row * DDIM + col) =
                    __floats2half2_rn(v00, v01);
                *reinterpret_cast<__half2*>(g_h + (size_t)(row + 8) * DDIM + col) =
                    __floats2half2_rn(v10, v11);
            } else {
                *reinterpret_cast<float2*>(outf + (size_t)row * DDIM + col) =
                    make_float2(v00, v01);
                *reinterpret_cast<float2*>(outf + (size_t)(row + 8) * DDIM + col) =
                    make_float2(v10, v11);
            }
        }
    }
}

extern "C" void kernel_launch(void* const* d_in, const int* in_sizes, int n_in,
                              void* d_out, int out_size) {
    const float* x = (const float*)d_in[0];
    const int* w1c = (const int*)d_in[1];
    const float* w1s = (const float*)d_in[2];
    const float* b1 = (const float*)d_in[3];
    const int* w2c = (const int*)d_in[4];
    const float* w2s = (const float*)d_in[5];
    const float* b2 = (const float*)d_in[6];
    float* out = (float*)d_out;

    cudaFuncSetAttribute(gemm_kernel<0>, cudaFuncAttributeMaxDynamicSharedMemorySize,
                         SMEM_BYTES);
    cudaFuncSetAttribute(gemm_kernel<1>, cudaFuncAttributeMaxDynamicSharedMemorySize,
                         SMEM_BYTES);

    const int dq_blocks = (DDIM * (size_t)DDIM / 4) / 256;
    dequant_kernel<<<dq_blocks, 256>>>(w1c, w1s, 0);
    dequant_kernel<<<dq_blocks, 256>>>(w2c, w2s, 1);

    const int sp_blocks = ((size_t)TDIM * DDIM / 4) / 256;
    split_kernel<<<sp_blocks, 256>>>(x);

    dim3 grid(DDIM / 256, TDIM / 128);
    gemm_kernel<0><<<grid, 256, SMEM_BYTES>>>(b1, nullptr);
    gemm_kernel<1><<<grid, 256, SMEM_BYTES>>>(b2, out);
}

// round 5
// speedup vs baseline: 1.3986x; 1.3986x over previous
#include <cuda_runtime.h>
#include <cuda_fp16.h>
#include <cstdint>

#define TDIM 8192
#define DDIM 4096

// ---- device scratch (allocation-free rule: __device__ globals) ----
static __device__ __half g_w1[(size_t)DDIM * DDIM];
static __device__ __half g_w2[(size_t)DDIM * DDIM];
static __device__ __half g_a[(size_t)TDIM * DDIM];
static __device__ __half g_h[(size_t)TDIM * DDIM];

__constant__ float c_lut[16] = {0.f, 0.5f, 1.f, 1.5f, 2.f, 3.f, 4.f, 6.f,
                                -0.f, -0.5f, -1.f, -1.5f, -2.f, -3.f, -4.f, -6.f};

// ---- dequant: int32 codes [D,D] * 2^scales [D,D/32] -> fp16 [D,D] (exact) ----
__global__ void dequant_kernel(const int* __restrict__ codes,
                               const float* __restrict__ scales,
                               int which) {
    __half* __restrict__ out = which ? g_w2 : g_w1;
    size_t base = ((size_t)blockIdx.x * blockDim.x + threadIdx.x) * 4;
    int4 c = *reinterpret_cast<const int4*>(codes + base);
    size_t o = base >> 12;
    int i = (int)(base & 4095);
    float s = __ldg(scales + o * (DDIM / 32) + (i >> 5));
    __half2 p0 = __floats2half2_rn(c_lut[c.x & 15] * s, c_lut[c.y & 15] * s);
    __half2 p1 = __floats2half2_rn(c_lut[c.z & 15] * s, c_lut[c.w & 15] * s);
    *reinterpret_cast<__half2*>(out + base) = p0;
    *reinterpret_cast<__half2*>(out + base + 2) = p1;
}

// ---- convert fp32 x -> fp16 ----
__global__ void split_kernel(const float* __restrict__ x) {
    size_t base = ((size_t)blockIdx.x * blockDim.x + threadIdx.x) * 4;
    float4 v = *reinterpret_cast<const float4*>(x + base);
    *reinterpret_cast<__half2*>(g_a + base) = __floats2half2_rn(v.x, v.y);
    *reinterpret_cast<__half2*>(g_a + base + 2) = __floats2half2_rn(v.z, v.w);
}

__device__ __forceinline__ void ldmat4(uint32_t addr, uint32_t& d0, uint32_t& d1,
                                       uint32_t& d2, uint32_t& d3) {
    asm volatile("ldmatrix.sync.aligned.m8n8.x4.shared.b16 {%0,%1,%2,%3}, [%4];\n"
                 : "=r"(d0), "=r"(d1), "=r"(d2), "=r"(d3) : "r"(addr));
}

__device__ __forceinline__ void mma16816(float* c, const uint32_t* a, const uint32_t* b) {
    asm volatile(
        "mma.sync.aligned.m16n8k16.row.col.f32.f16.f16.f32 "
        "{%0,%1,%2,%3}, {%4,%5,%6,%7}, {%8,%9}, {%0,%1,%2,%3};\n"
        : "+f"(c[0]), "+f"(c[1]), "+f"(c[2]), "+f"(c[3])
        : "r"(a[0]), "r"(a[1]), "r"(a[2]), "r"(a[3]), "r"(b[0]), "r"(b[1]));
}

// XOR-swizzled smem offset (bytes): 64B rows of 4x16B chunks;
// chunk ^= (row>>1)&3 -> conflict-free for STS.128 and ldmatrix.
__device__ __forceinline__ uint32_t swoff(int row, int kchunk) {
    return (uint32_t)(row * 64 + ((kchunk ^ ((row >> 1) & 3)) << 4));
}

// ================= GEMM: 128(M) x 256(N) CTA, BK=32, 2-stage smem =========
// 8 warps = 2(M) x 4(N), 64x64 per warp. One __syncthreads per chunk.
#define BK 32
#define NCH (DDIM / BK)
#define W_BYTES (256 * BK * 2)
#define A_BYTES (128 * BK * 2)
#define STAGE_BYTES (W_BYTES + A_BYTES)
#define SMEM_BYTES (2 * STAGE_BYTES)

template <int LAYER>
__global__ void __launch_bounds__(256, 1)
gemm_kernel(const float* __restrict__ bias, float* __restrict__ outf) {
    extern __shared__ char dsm[];
    const __half* __restrict__ A = (LAYER == 0) ? g_a : g_h;
    const __half* __restrict__ W = (LAYER == 0) ? g_w1 : g_w2;

    __shared__ float sBias[256];

    const int tid = threadIdx.x;
    const int lane = tid & 31;
    const int wid = tid >> 5;
    const int wm = wid & 1;
    const int wn = wid >> 1;
    const int o0 = blockIdx.x * 256;
    const int t0 = blockIdx.y * 128;

    sBias[tid] = __ldg(bias + o0 + tid);

    const uint32_t sdyn = (uint32_t)__cvta_generic_to_shared(dsm);

    // loader map: thread -> (row r0 + 64*i, 16B chunk c)
    const int r0 = tid >> 2;
    const int c = tid & 3;
    const __half* gW = W + (size_t)(o0 + r0) * DDIM + c * 8;
    const __half* gA = A + (size_t)(t0 + r0) * DDIM + c * 8;
    uint32_t stW[4], stA[2];
#pragma unroll
    for (int i = 0; i < 4; i++) stW[i] = swoff(r0 + 64 * i, c);
#pragma unroll
    for (int i = 0; i < 2; i++) stA[i] = A_BYTES ? swoff(r0 + 64 * i, c) : 0;

    float acc[4][8][4];
#pragma unroll
    for (int i = 0; i < 4; i++)
#pragma unroll
        for (int j = 0; j < 8; j++)
#pragma unroll
            for (int k = 0; k < 4; k++) acc[i][j][k] = 0.f;

    // ldmatrix lane address components
    const int aRow = lane & 15;
    const int aKC = lane >> 4;
    const int bRow = (lane & 7) + ((lane >> 4) << 3);
    const int bKC = (lane >> 3) & 1;
    uint32_t aOff[4];
    int aXor[4];
#pragma unroll
    for (int mf = 0; mf < 4; mf++) {
        int row = wm * 64 + mf * 16 + aRow;
        aOff[mf] = (uint32_t)(row * 64);
        aXor[mf] = (row >> 1) & 3;
    }
    uint32_t bOff[4];
    int bXor[4];
#pragma unroll
    for (int nb = 0; nb < 4; nb++) {
        int row = wn * 64 + nb * 16 + bRow;
        bOff[nb] = (uint32_t)(row * 64);
        bXor[nb] = (row >> 1) & 3;
    }

    uint4 rw[4], ra[2];
    auto ldg_chunk = [&]() {
#pragma unroll
        for (int i = 0; i < 4; i++)
            rw[i] = *reinterpret_cast<const uint4*>(gW + (size_t)i * 64 * DDIM);
#pragma unroll
        for (int i = 0; i < 2; i++)
            ra[i] = *reinterpret_cast<const uint4*>(gA + (size_t)i * 64 * DDIM);
        gW += BK;
        gA += BK;
    };
    auto sts_chunk = [&](int buf) {
        char* wb = dsm + buf * STAGE_BYTES;
        char* ab = wb + W_BYTES;
#pragma unroll
        for (int i = 0; i < 4; i++) *reinterpret_cast<uint4*>(wb + stW[i]) = rw[i];
#pragma unroll
        for (int i = 0; i < 2; i++) *reinterpret_cast<uint4*>(ab + stA[i]) = ra[i];
    };

    // prologue: chunk0 -> buf0, prefetch chunk1 into regs
    ldg_chunk();
    sts_chunk(0);
    ldg_chunk();
    __syncthreads();

    for (int i = 0; i < NCH; i++) {
        const int b = i & 1;
        const uint32_t wb = sdyn + b * STAGE_BYTES;
        const uint32_t ab = wb + W_BYTES;

        // kstep 0 fragments
        uint32_t a0[4][4], b0[8][2];
#pragma unroll
        for (int nb = 0; nb < 4; nb++) {
            uint32_t addr = wb + bOff[nb] + (uint32_t)((bKC ^ bXor[nb]) << 4);
            ldmat4(addr, b0[nb * 2][0], b0[nb * 2][1], b0[nb * 2 + 1][0],
                   b0[nb * 2 + 1][1]);
        }
#pragma unroll
        for (int mf = 0; mf < 4; mf++) {
            uint32_t addr = ab + aOff[mf] + (uint32_t)((aKC ^ aXor[mf]) << 4);
            ldmat4(addr, a0[mf][0], a0[mf][1], a0[mf][2], a0[mf][3]);
        }

        // store chunk i+1 into other buffer (overlaps with MMAs below)
        if (i + 1 < NCH) sts_chunk(b ^ 1);
        // prefetch chunk i+2 from gmem (2-chunk lookahead)
        if (i + 2 < NCH) ldg_chunk();

        // kstep 1 fragments
        uint32_t a1[4][4], b1[8][2];
#pragma unroll
        for (int nb = 0; nb < 4; nb++) {
            uint32_t addr = wb + bOff[nb] + (uint32_t)(((2 + bKC) ^ bXor[nb]) << 4);
            ldmat4(addr, b1[nb * 2][0], b1[nb * 2][1], b1[nb * 2 + 1][0],
                   b1[nb * 2 + 1][1]);
        }
#pragma unroll
        for (int mf = 0; mf < 4; mf++) {
            uint32_t addr = ab + aOff[mf] + (uint32_t)(((2 + aKC) ^ aXor[mf]) << 4);
            ldmat4(addr, a1[mf][0], a1[mf][1], a1[mf][2], a1[mf][3]);
        }

        // MMAs (STS/LDG/LDSM latency hides underneath)
#pragma unroll
        for (int mf = 0; mf < 4; mf++)
#pragma unroll
            for (int nf = 0; nf < 8; nf++) mma16816(acc[mf][nf], a0[mf], b0[nf]);
#pragma unroll
        for (int mf = 0; mf < 4; mf++)
#pragma unroll
            for (int nf = 0; nf < 8; nf++) mma16816(acc[mf][nf], a1[mf], b1[nf]);

        __syncthreads();
    }

    // ---- epilogue ----
    const int gr = lane >> 2;
    const int tc2 = (lane & 3) * 2;
#pragma unroll
    for (int mf = 0; mf < 4; mf++) {
        const int row = t0 + wm * 64 + mf * 16 + gr;
#pragma unroll
        for (int nf = 0; nf < 8; nf++) {
            const int colL = wn * 64 + nf * 8 + tc2;
            const int col = o0 + colL;
            float bv0 = sBias[colL];
            float bv1 = sBias[colL + 1];
            float v00 = acc[mf][nf][0] + bv0;
            float v01 = acc[mf][nf][1] + bv1;
            float v10 = acc[mf][nf][2] + bv0;
            float v11 = acc[mf][nf][3] + bv1;
            if (LAYER == 0) {
                *reinterpret_cast<__half2*>(g_h + (size_t)row * DDIM + col) =
                    __floats2half2_rn(v00, v01);
                *reinterpret_cast<__half2*>(g_h + (size_t)(row + 8) * DDIM + col) =
                    __floats2half2_rn(v10, v11);
            } else {
                *reinterpret_cast<float2*>(outf + (size_t)row * DDIM + col) =
                    make_float2(v00, v01);
                *reinterpret_cast<float2*>(outf + (size_t)(row + 8) * DDIM + col) =
                    make_float2(v10, v11);
            }
        }
    }
}

extern "C" void kernel_launch(void* const* d_in, const int* in_sizes, int n_in,
                              void* d_out, int out_size) {
    const float* x = (const float*)d_in[0];
    const int* w1c = (const int*)d_in[1];
    const float* w1s = (const float*)d_in[2];
    const float* b1 = (const float*)d_in[3];
    const int* w2c = (const int*)d_in[4];
    const float* w2s = (const float*)d_in[5];
    const float* b2 = (const float*)d_in[6];
    float* out = (float*)d_out;

    cudaFuncSetAttribute(gemm_kernel<0>, cudaFuncAttributeMaxDynamicSharedMemorySize,
                         SMEM_BYTES);
    cudaFuncSetAttribute(gemm_kernel<1>, cudaFuncAttributeMaxDynamicSharedMemorySize,
                         SMEM_BYTES);

    const int dq_blocks = (DDIM * (size_t)DDIM / 4) / 256;
    dequant_kernel<<<dq_blocks, 256>>>(w1c, w1s, 0);
    dequant_kernel<<<dq_blocks, 256>>>(w2c, w2s, 1);

    const int sp_blocks = ((size_t)TDIM * DDIM / 4) / 256;
    split_kernel<<<sp_blocks, 256>>>(x);

    dim3 grid(DDIM / 256, TDIM / 128);
    gemm_kernel<0><<<grid, 256, SMEM_BYTES>>>(b1, nullptr);
    gemm_kernel<1><<<grid, 256, SMEM_BYTES>>>(b2, out);
}

// round 6
// speedup vs baseline: 1.6238x; 1.1610x over previous
#include <cuda_runtime.h>
#include <cuda_fp16.h>
#include <cstdint>

#define TDIM 8192
#define DDIM 4096

// ---- device scratch (allocation-free rule: __device__ globals) ----
static __device__ __half g_w1[(size_t)DDIM * DDIM];
static __device__ __half g_w2[(size_t)DDIM * DDIM];
static __device__ __half g_a[(size_t)TDIM * DDIM];
static __device__ __half g_h[(size_t)TDIM * DDIM];

__constant__ float c_lut[16] = {0.f, 0.5f, 1.f, 1.5f, 2.f, 3.f, 4.f, 6.f,
                                -0.f, -0.5f, -1.f, -1.5f, -2.f, -3.f, -4.f, -6.f};

// ---- dequant: int32 codes [D,D] * 2^scales [D,D/32] -> fp16 [D,D] (exact) ----
__global__ void dequant_kernel(const int* __restrict__ codes,
                               const float* __restrict__ scales,
                               int which) {
    __half* __restrict__ out = which ? g_w2 : g_w1;
    size_t base = ((size_t)blockIdx.x * blockDim.x + threadIdx.x) * 4;
    int4 c = *reinterpret_cast<const int4*>(codes + base);
    size_t o = base >> 12;
    int i = (int)(base & 4095);
    float s = __ldg(scales + o * (DDIM / 32) + (i >> 5));
    __half2 p0 = __floats2half2_rn(c_lut[c.x & 15] * s, c_lut[c.y & 15] * s);
    __half2 p1 = __floats2half2_rn(c_lut[c.z & 15] * s, c_lut[c.w & 15] * s);
    *reinterpret_cast<__half2*>(out + base) = p0;
    *reinterpret_cast<__half2*>(out + base + 2) = p1;
}

// ---- convert fp32 x -> fp16 ----
__global__ void split_kernel(const float* __restrict__ x) {
    size_t base = ((size_t)blockIdx.x * blockDim.x + threadIdx.x) * 4;
    float4 v = *reinterpret_cast<const float4*>(x + base);
    *reinterpret_cast<__half2*>(g_a + base) = __floats2half2_rn(v.x, v.y);
    *reinterpret_cast<__half2*>(g_a + base + 2) = __floats2half2_rn(v.z, v.w);
}

__device__ __forceinline__ void ldmat4(uint32_t addr, uint32_t& d0, uint32_t& d1,
                                       uint32_t& d2, uint32_t& d3) {
    asm volatile("ldmatrix.sync.aligned.m8n8.x4.shared.b16 {%0,%1,%2,%3}, [%4];\n"
                 : "=r"(d0), "=r"(d1), "=r"(d2), "=r"(d3) : "r"(addr));
}

__device__ __forceinline__ void mma16816(float* c, const uint32_t* a, const uint32_t* b) {
    asm volatile(
        "mma.sync.aligned.m16n8k16.row.col.f32.f16.f16.f32 "
        "{%0,%1,%2,%3}, {%4,%5,%6,%7}, {%8,%9}, {%0,%1,%2,%3};\n"
        : "+f"(c[0]), "+f"(c[1]), "+f"(c[2]), "+f"(c[3])
        : "r"(a[0]), "r"(a[1]), "r"(a[2]), "r"(a[3]), "r"(b[0]), "r"(b[1]));
}

__device__ __forceinline__ void cp16(uint32_t saddr, const void* gaddr) {
    asm volatile("cp.async.cg.shared.global [%0], [%1], 16;\n"
                 :: "r"(saddr), "l"(gaddr));
}

// XOR-swizzled smem offset (bytes): 64B rows of 4x16B chunks;
// chunk ^= (row>>1)&3 -> conflict-free for writes and ldmatrix.
__device__ __forceinline__ uint32_t swoff(int row, int kchunk) {
    return (uint32_t)(row * 64 + ((kchunk ^ ((row >> 1) & 3)) << 4));
}

// ====== GEMM: 128(M) x 256(N) CTA, BK=32, 3-stage cp.async, frag pipeline ===
#define BK 32
#define STAGES 3
#define NCH (DDIM / BK)
#define W_BYTES (256 * BK * 2)
#define A_BYTES (128 * BK * 2)
#define STAGE_BYTES (W_BYTES + A_BYTES)
#define SMEM_BYTES (STAGES * STAGE_BYTES)

template <int LAYER>
__global__ void __launch_bounds__(256, 1)
gemm_kernel(const float* __restrict__ bias, float* __restrict__ outf) {
    extern __shared__ char dsm[];
    const __half* __restrict__ A = (LAYER == 0) ? g_a : g_h;
    const __half* __restrict__ W = (LAYER == 0) ? g_w1 : g_w2;

    __shared__ float sBias[256];

    const int tid = threadIdx.x;
    const int lane = tid & 31;
    const int wid = tid >> 5;
    const int wm = wid & 1;
    const int wn = wid >> 1;
    const int o0 = blockIdx.x * 256;
    const int t0 = blockIdx.y * 128;

    sBias[tid] = __ldg(bias + o0 + tid);

    const uint32_t sdyn = (uint32_t)__cvta_generic_to_shared(dsm);

    // loader map: thread -> (row r0 + 64*i, 16B chunk c)
    const int r0 = tid >> 2;
    const int c = tid & 3;
    const __half* pW[4];
    const __half* pA[2];
#pragma unroll
    for (int i = 0; i < 4; i++)
        pW[i] = W + (size_t)(o0 + r0 + 64 * i) * DDIM + c * 8;
#pragma unroll
    for (int i = 0; i < 2; i++)
        pA[i] = A + (size_t)(t0 + r0 + 64 * i) * DDIM + c * 8;
    uint32_t stW[4], stA[2];
#pragma unroll
    for (int i = 0; i < 4; i++) stW[i] = swoff(r0 + 64 * i, c);
#pragma unroll
    for (int i = 0; i < 2; i++) stA[i] = swoff(r0 + 64 * i, c);

    auto load_stage = [&](int s, int k0) {
        const uint32_t wb = sdyn + s * STAGE_BYTES;
        const uint32_t ab = wb + W_BYTES;
#pragma unroll
        for (int i = 0; i < 4; i++) cp16(wb + stW[i], pW[i] + k0);
#pragma unroll
        for (int i = 0; i < 2; i++) cp16(ab + stA[i], pA[i] + k0);
        asm volatile("cp.async.commit_group;\n" ::: "memory");
    };

    // ---- mma fragment address components ----
    const int aRow = lane & 15;
    const int aKC = lane >> 4;
    const int bRow = (lane & 7) + ((lane >> 4) << 3);
    const int bKC = (lane >> 3) & 1;
    uint32_t aOff[4];
    int aXor[4];
#pragma unroll
    for (int mf = 0; mf < 4; mf++) {
        int row = wm * 64 + mf * 16 + aRow;
        aOff[mf] = (uint32_t)(row * 64);
        aXor[mf] = (row >> 1) & 3;
    }
    uint32_t bOff[4];
    int bXor[4];
#pragma unroll
    for (int nb = 0; nb < 4; nb++) {
        int row = wn * 64 + nb * 16 + bRow;
        bOff[nb] = (uint32_t)(row * 64);
        bXor[nb] = (row >> 1) & 3;
    }

    float acc[4][8][4];
#pragma unroll
    for (int i = 0; i < 4; i++)
#pragma unroll
        for (int j = 0; j < 8; j++)
#pragma unroll
            for (int k = 0; k < 4; k++) acc[i][j][k] = 0.f;

    uint32_t a0[4][4], b0[8][2], a1[4][4], b1[8][2];

    // fragment loaders: kc = 16B-chunk index of kstep (0 or 2)
    auto ldsm0 = [&](uint32_t wb, uint32_t ab, int kc) {
#pragma unroll
        for (int nb = 0; nb < 4; nb++) {
            uint32_t addr = wb + bOff[nb] + (uint32_t)(((kc + bKC) ^ bXor[nb]) << 4);
            ldmat4(addr, b0[nb * 2][0], b0[nb * 2][1], b0[nb * 2 + 1][0],
                   b0[nb * 2 + 1][1]);
        }
#pragma unroll
        for (int mf = 0; mf < 4; mf++) {
            uint32_t addr = ab + aOff[mf] + (uint32_t)(((kc + aKC) ^ aXor[mf]) << 4);
            ldmat4(addr, a0[mf][0], a0[mf][1], a0[mf][2], a0[mf][3]);
        }
    };
    auto ldsm1 = [&](uint32_t wb, uint32_t ab, int kc) {
#pragma unroll
        for (int nb = 0; nb < 4; nb++) {
            uint32_t addr = wb + bOff[nb] + (uint32_t)(((kc + bKC) ^ bXor[nb]) << 4);
            ldmat4(addr, b1[nb * 2][0], b1[nb * 2][1], b1[nb * 2 + 1][0],
                   b1[nb * 2 + 1][1]);
        }
#pragma unroll
        for (int mf = 0; mf < 4; mf++) {
            uint32_t addr = ab + aOff[mf] + (uint32_t)(((kc + aKC) ^ aXor[mf]) << 4);
            ldmat4(addr, a1[mf][0], a1[mf][1], a1[mf][2], a1[mf][3]);
        }
    };

    // prologue: chunks 0,1 in flight; wait chunk0; preload its kstep0 frags
    load_stage(0, 0);
    load_stage(1, BK);
    asm volatile("cp.async.wait_group 1;\n" ::: "memory");
    __syncthreads();
    ldsm0(sdyn, sdyn + W_BYTES, 0);

    for (int i = 0; i < NCH; i++) {
        const int s = i % STAGES;
        const uint32_t wb = sdyn + s * STAGE_BYTES;
        const uint32_t ab = wb + W_BYTES;

        // kstep1 fragments of this chunk (latency covered by MMA f0 below)
        ldsm1(wb, ab, 2);

        // async-load chunk i+2 into stage (i+2)%STAGES
        if (i + 2 < NCH) load_stage((i + 2) % STAGES, (i + 2) * BK);

        // MMA on kstep0 (frags were preloaded last iteration)
#pragma unroll
        for (int mf = 0; mf < 4; mf++)
#pragma unroll
            for (int nf = 0; nf < 8; nf++) mma16816(acc[mf][nf], a0[mf], b0[nf]);

        // make chunk i+1 visible; also orders stage reuse
        if (i + 2 < NCH)
            asm volatile("cp.async.wait_group 1;\n" ::: "memory");
        else
            asm volatile("cp.async.wait_group 0;\n" ::: "memory");
        __syncthreads();

        // preload kstep0 frags of chunk i+1 (latency covered by MMA f1 below)
        if (i + 1 < NCH) {
            const uint32_t wbn = sdyn + ((i + 1) % STAGES) * STAGE_BYTES;
            ldsm0(wbn, wbn + W_BYTES, 0);
        }

        // MMA on kstep1
#pragma unroll
        for (int mf = 0; mf < 4; mf++)
#pragma unroll
            for (int nf = 0; nf < 8; nf++) mma16816(acc[mf][nf], a1[mf], b1[nf]);
    }

    // ---- epilogue ----
    const int gr = lane >> 2;
    const int tc2 = (lane & 3) * 2;
#pragma unroll
    for (int mf = 0; mf < 4; mf++) {
        const int row = t0 + wm * 64 + mf * 16 + gr;
#pragma unroll
        for (int nf = 0; nf < 8; nf++) {
            const int colL = wn * 64 + nf * 8 + tc2;
            const int col = o0 + colL;
            float bv0 = sBias[colL];
            float bv1 = sBias[colL + 1];
            float v00 = acc[mf][nf][0] + bv0;
            float v01 = acc[mf][nf][1] + bv1;
            float v10 = acc[mf][nf][2] + bv0;
            float v11 = acc[mf][nf][3] + bv1;
            if (LAYER == 0) {
                *reinterpret_cast<__half2*>(g_h + (size_t)row * DDIM + col) =
                    __floats2half2_rn(v00, v01);
                *reinterpret_cast<__half2*>(g_h + (size_t)(row + 8) * DDIM + col) =
                    __floats2half2_rn(v10, v11);
            } else {
                *reinterpret_cast<float2*>(outf + (size_t)row * DDIM + col) =
                    make_float2(v00, v01);
                *reinterpret_cast<float2*>(outf + (size_t)(row + 8) * DDIM + col) =
                    make_float2(v10, v11);
            }
        }
    }
}

extern "C" void kernel_launch(void* const* d_in, const int* in_sizes, int n_in,
                              void* d_out, int out_size) {
    const float* x = (const float*)d_in[0];
    const int* w1c = (const int*)d_in[1];
    const float* w1s = (const float*)d_in[2];
    const float* b1 = (const float*)d_in[3];
    const int* w2c = (const int*)d_in[4];
    const float* w2s = (const float*)d_in[5];
    const float* b2 = (const float*)d_in[6];
    float* out = (float*)d_out;

    cudaFuncSetAttribute(gemm_kernel<0>, cudaFuncAttributeMaxDynamicSharedMemorySize,
                         SMEM_BYTES);
    cudaFuncSetAttribute(gemm_kernel<1>, cudaFuncAttributeMaxDynamicSharedMemorySize,
                         SMEM_BYTES);

    const int dq_blocks = (DDIM * (size_t)DDIM / 4) / 256;
    dequant_kernel<<<dq_blocks, 256>>>(w1c, w1s, 0);
    dequant_kernel<<<dq_blocks, 256>>>(w2c, w2s, 1);

    const int sp_blocks = ((size_t)TDIM * DDIM / 4) / 256;
    split_kernel<<<sp_blocks, 256>>>(x);

    dim3 grid(DDIM / 256, TDIM / 128);
    gemm_kernel<0><<<grid, 256, SMEM_BYTES>>>(b1, nullptr);
    gemm_kernel<1><<<grid, 256, SMEM_BYTES>>>(b2, out);
}

// round 7
// speedup vs baseline: 1.8695x; 1.1513x over previous
#include <cuda_runtime.h>
#include <cuda_fp16.h>
#include <cstdint>

#define TDIM 8192
#define DDIM 4096

// ---- device scratch (allocation-free rule: __device__ globals) ----
static __device__ __half g_w1[(size_t)DDIM * DDIM];
static __device__ __half g_w2[(size_t)DDIM * DDIM];
static __device__ __half g_a[(size_t)TDIM * DDIM];
static __device__ __half g_h[(size_t)TDIM * DDIM];

__constant__ float c_lut[16] = {0.f, 0.5f, 1.f, 1.5f, 2.f, 3.f, 4.f, 6.f,
                                -0.f, -0.5f, -1.f, -1.5f, -2.f, -3.f, -4.f, -6.f};

// ---- dequant: int32 codes [D,D] * 2^scales [D,D/32] -> fp16 [D,D] (exact) ----
__global__ void dequant_kernel(const int* __restrict__ codes,
                               const float* __restrict__ scales,
                               int which) {
    __half* __restrict__ out = which ? g_w2 : g_w1;
    size_t base = ((size_t)blockIdx.x * blockDim.x + threadIdx.x) * 4;
    int4 c = *reinterpret_cast<const int4*>(codes + base);
    size_t o = base >> 12;
    int i = (int)(base & 4095);
    float s = __ldg(scales + o * (DDIM / 32) + (i >> 5));
    __half2 p0 = __floats2half2_rn(c_lut[c.x & 15] * s, c_lut[c.y & 15] * s);
    __half2 p1 = __floats2half2_rn(c_lut[c.z & 15] * s, c_lut[c.w & 15] * s);
    *reinterpret_cast<__half2*>(out + base) = p0;
    *reinterpret_cast<__half2*>(out + base + 2) = p1;
}

// ---- convert fp32 x -> fp16 ----
__global__ void split_kernel(const float* __restrict__ x) {
    size_t base = ((size_t)blockIdx.x * blockDim.x + threadIdx.x) * 4;
    float4 v = *reinterpret_cast<const float4*>(x + base);
    *reinterpret_cast<__half2*>(g_a + base) = __floats2half2_rn(v.x, v.y);
    *reinterpret_cast<__half2*>(g_a + base + 2) = __floats2half2_rn(v.z, v.w);
}

__device__ __forceinline__ void ldmat4(uint32_t addr, uint32_t& d0, uint32_t& d1,
                                       uint32_t& d2, uint32_t& d3) {
    asm volatile("ldmatrix.sync.aligned.m8n8.x4.shared.b16 {%0,%1,%2,%3}, [%4];\n"
                 : "=r"(d0), "=r"(d1), "=r"(d2), "=r"(d3) : "r"(addr));
}

__device__ __forceinline__ void mma16816(float* c, const uint32_t* a, const uint32_t* b) {
    asm volatile(
        "mma.sync.aligned.m16n8k16.row.col.f32.f16.f16.f32 "
        "{%0,%1,%2,%3}, {%4,%5,%6,%7}, {%8,%9}, {%0,%1,%2,%3};\n"
        : "+f"(c[0]), "+f"(c[1]), "+f"(c[2]), "+f"(c[3])
        : "r"(a[0]), "r"(a[1]), "r"(a[2]), "r"(a[3]), "r"(b[0]), "r"(b[1]));
}

__device__ __forceinline__ void cp16(uint32_t saddr, const void* gaddr) {
    asm volatile("cp.async.cg.shared.global [%0], [%1], 16;\n"
                 :: "r"(saddr), "l"(gaddr));
}

// XOR-swizzled smem offset (bytes): 64B rows of 4x16B chunks;
// chunk ^= (row>>1)&3 -> conflict-free for writes and ldmatrix.
__device__ __forceinline__ uint32_t swoff(int row, int kchunk) {
    return (uint32_t)(row * 64 + ((kchunk ^ ((row >> 1) & 3)) << 4));
}

// ====== GEMM: 128(M) x 256(N) CTA, BK=32, 3-stage cp.async, interleaved ====
#define BK 32
#define STAGES 3
#define NCH (DDIM / BK)
#define W_BYTES (256 * BK * 2)
#define A_BYTES (128 * BK * 2)
#define STAGE_BYTES (W_BYTES + A_BYTES)
#define SMEM_BYTES (STAGES * STAGE_BYTES)

template <int LAYER>
__global__ void __launch_bounds__(256, 1)
gemm_kernel(const float* __restrict__ bias, float* __restrict__ outf) {
    extern __shared__ char dsm[];
    const __half* __restrict__ A = (LAYER == 0) ? g_a : g_h;
    const __half* __restrict__ W = (LAYER == 0) ? g_w1 : g_w2;

    __shared__ float sBias[256];

    const int tid = threadIdx.x;
    const int lane = tid & 31;
    const int wid = tid >> 5;
    const int wm = wid & 1;
    const int wn = wid >> 1;
    const int o0 = blockIdx.x * 256;
    const int t0 = blockIdx.y * 128;

    sBias[tid] = __ldg(bias + o0 + tid);

    const uint32_t sdyn = (uint32_t)__cvta_generic_to_shared(dsm);

    // loader map: thread -> (row r0 + 64*i, 16B chunk c)
    const int r0 = tid >> 2;
    const int c = tid & 3;
    const __half* pW[4];
    const __half* pA[2];
#pragma unroll
    for (int i = 0; i < 4; i++)
        pW[i] = W + (size_t)(o0 + r0 + 64 * i) * DDIM + c * 8;
#pragma unroll
    for (int i = 0; i < 2; i++)
        pA[i] = A + (size_t)(t0 + r0 + 64 * i) * DDIM + c * 8;
    uint32_t stW[4], stA[2];
#pragma unroll
    for (int i = 0; i < 4; i++) stW[i] = swoff(r0 + 64 * i, c);
#pragma unroll
    for (int i = 0; i < 2; i++) stA[i] = swoff(r0 + 64 * i, c);

    // ---- mma fragment address components ----
    const int aRow = lane & 15;
    const int aKC = lane >> 4;
    const int bRow = (lane & 7) + ((lane >> 4) << 3);
    const int bKC = (lane >> 3) & 1;
    uint32_t aOff[4];
    int aXor[4];
#pragma unroll
    for (int mf = 0; mf < 4; mf++) {
        int row = wm * 64 + mf * 16 + aRow;
        aOff[mf] = (uint32_t)(row * 64);
        aXor[mf] = (row >> 1) & 3;
    }
    uint32_t bOff[4];
    int bXor[4];
#pragma unroll
    for (int nb = 0; nb < 4; nb++) {
        int row = wn * 64 + nb * 16 + bRow;
        bOff[nb] = (uint32_t)(row * 64);
        bXor[nb] = (row >> 1) & 3;
    }

    float acc[4][8][4];
#pragma unroll
    for (int i = 0; i < 4; i++)
#pragma unroll
        for (int j = 0; j < 8; j++)
#pragma unroll
            for (int k = 0; k < 4; k++) acc[i][j][k] = 0.f;

    uint32_t a0[4][4], b0[8][2], a1[4][4], b1[8][2];

    // single-ldmatrix piece loaders (kc: 0 = kstep0, 2 = kstep1)
    auto ldB = [&](uint32_t (*b)[2], uint32_t wb, int nb, int kc) {
        uint32_t addr = wb + bOff[nb] + (uint32_t)(((kc + bKC) ^ bXor[nb]) << 4);
        ldmat4(addr, b[nb * 2][0], b[nb * 2][1], b[nb * 2 + 1][0], b[nb * 2 + 1][1]);
    };
    auto ldA = [&](uint32_t (*a)[4], uint32_t ab, int mf, int kc) {
        uint32_t addr = ab + aOff[mf] + (uint32_t)(((kc + aKC) ^ aXor[mf]) << 4);
        ldmat4(addr, a[mf][0], a[mf][1], a[mf][2], a[mf][3]);
    };
    auto mma8 = [&](float (*accrow)[4], const uint32_t* a, uint32_t (*b)[2]) {
#pragma unroll
        for (int nf = 0; nf < 8; nf++) mma16816(accrow[nf], a, b[nf]);
    };

    // prologue: chunks 0,1 in flight; wait chunk0; preload its kstep0 frags
    {
        const uint32_t wb0 = sdyn, ab0 = sdyn + W_BYTES;
        const uint32_t wb1 = sdyn + STAGE_BYTES, ab1 = wb1 + W_BYTES;
#pragma unroll
        for (int i = 0; i < 4; i++) cp16(wb0 + stW[i], pW[i]);
#pragma unroll
        for (int i = 0; i < 2; i++) cp16(ab0 + stA[i], pA[i]);
        asm volatile("cp.async.commit_group;\n" ::: "memory");
#pragma unroll
        for (int i = 0; i < 4; i++) cp16(wb1 + stW[i], pW[i] + BK);
#pragma unroll
        for (int i = 0; i < 2; i++) cp16(ab1 + stA[i], pA[i] + BK);
        asm volatile("cp.async.commit_group;\n" ::: "memory");
        asm volatile("cp.async.wait_group 1;\n" ::: "memory");
        __syncthreads();
#pragma unroll
        for (int nb = 0; nb < 4; nb++) ldB(b0, wb0, nb, 0);
#pragma unroll
        for (int mf = 0; mf < 4; mf++) ldA(a0, ab0, mf, 0);
    }

    for (int i = 0; i < NCH; i++) {
        const uint32_t wb = sdyn + (i % STAGES) * STAGE_BYTES;
        const uint32_t ab = wb + W_BYTES;
        const uint32_t wbn = sdyn + ((i + 1) % STAGES) * STAGE_BYTES;
        const uint32_t abn = wbn + W_BYTES;
        const uint32_t wbL = sdyn + ((i + 2) % STAGES) * STAGE_BYTES;
        const uint32_t abL = wbL + W_BYTES;
        const int k2 = (i + 2) * BK;
        const bool haveNext = (i + 1 < NCH);
        const bool load2 = (i + 2 < NCH);

        // ---- Phase A: MMA f0 interleaved with ldsm(f1) + cp.async ----
        ldB(b1, wb, 0, 2);
        ldB(b1, wb, 1, 2);
        mma8(acc[0], a0[0], b0);
        if (load2) { cp16(wbL + stW[0], pW[0] + k2); cp16(wbL + stW[1], pW[1] + k2); }
        ldB(b1, wb, 2, 2);
        ldB(b1, wb, 3, 2);
        mma8(acc[1], a0[1], b0);
        if (load2) { cp16(wbL + stW[2], pW[2] + k2); cp16(wbL + stW[3], pW[3] + k2); }
        ldA(a1, ab, 0, 2);
        ldA(a1, ab, 1, 2);
        mma8(acc[2], a0[2], b0);
        if (load2) {
            cp16(abL + stA[0], pA[0] + k2);
            cp16(abL + stA[1], pA[1] + k2);
        }
        ldA(a1, ab, 2, 2);
        ldA(a1, ab, 3, 2);
        mma8(acc[3], a0[3], b0);
        if (load2) asm volatile("cp.async.commit_group;\n" ::: "memory");

        // ---- Phase B: MMA f1; barrier mid-phase; preload next kstep0 frags ----
        mma8(acc[0], a1[0], b1);
        mma8(acc[1], a1[1], b1);
        if (load2)
            asm volatile("cp.async.wait_group 1;\n" ::: "memory");
        else
            asm volatile("cp.async.wait_group 0;\n" ::: "memory");
        __syncthreads();
        if (haveNext) { ldB(b0, wbn, 0, 0); ldB(b0, wbn, 1, 0); }
        mma8(acc[2], a1[2], b1);
        if (haveNext) {
            ldB(b0, wbn, 2, 0);
            ldB(b0, wbn, 3, 0);
            ldA(a0, abn, 0, 0);
            ldA(a0, abn, 1, 0);
        }
        mma8(acc[3], a1[3], b1);
        if (haveNext) {
            ldA(a0, abn, 2, 0);
            ldA(a0, abn, 3, 0);
        }
    }

    // ---- epilogue ----
    const int gr = lane >> 2;
    const int tc2 = (lane & 3) * 2;
#pragma unroll
    for (int mf = 0; mf < 4; mf++) {
        const int row = t0 + wm * 64 + mf * 16 + gr;
#pragma unroll
        for (int nf = 0; nf < 8; nf++) {
            const int colL = wn * 64 + nf * 8 + tc2;
            const int col = o0 + colL;
            float bv0 = sBias[colL];
            float bv1 = sBias[colL + 1];
            float v00 = acc[mf][nf][0] + bv0;
            float v01 = acc[mf][nf][1] + bv1;
            float v10 = acc[mf][nf][2] + bv0;
            float v11 = acc[mf][nf][3] + bv1;
            if (LAYER == 0) {
                *reinterpret_cast<__half2*>(g_h + (size_t)row * DDIM + col) =
                    __floats2half2_rn(v00, v01);
                *reinterpret_cast<__half2*>(g_h + (size_t)(row + 8) * DDIM + col) =
                    __floats2half2_rn(v10, v11);
            } else {
                *reinterpret_cast<float2*>(outf + (size_t)row * DDIM + col) =
                    make_float2(v00, v01);
                *reinterpret_cast<float2*>(outf + (size_t)(row + 8) * DDIM + col) =
                    make_float2(v10, v11);
            }
        }
    }
}

extern "C" void kernel_launch(void* const* d_in, const int* in_sizes, int n_in,
                              void* d_out, int out_size) {
    const float* x = (const float*)d_in[0];
    const int* w1c = (const int*)d_in[1];
    const float* w1s = (const float*)d_in[2];
    const float* b1 = (const float*)d_in[3];
    const int* w2c = (const int*)d_in[4];
    const float* w2s = (const float*)d_in[5];
    const float* b2 = (const float*)d_in[6];
    float* out = (float*)d_out;

    cudaFuncSetAttribute(gemm_kernel<0>, cudaFuncAttributeMaxDynamicSharedMemorySize,
                         SMEM_BYTES);
    cudaFuncSetAttribute(gemm_kernel<1>, cudaFuncAttributeMaxDynamicSharedMemorySize,
                         SMEM_BYTES);

    const int dq_blocks = (DDIM * (size_t)DDIM / 4) / 256;
    dequant_kernel<<<dq_blocks, 256>>>(w1c, w1s, 0);
    dequant_kernel<<<dq_blocks, 256>>>(w2c, w2s, 1);

    const int sp_blocks = ((size_t)TDIM * DDIM / 4) / 256;
    split_kernel<<<sp_blocks, 256>>>(x);

    dim3 grid(DDIM / 256, TDIM / 128);
    gemm_kernel<0><<<grid, 256, SMEM_BYTES>>>(b1, nullptr);
    gemm_kernel<1><<<grid, 256, SMEM_BYTES>>>(b2, out);
}